// round 9
// baseline (speedup 1.0000x reference)
#include <cuda_runtime.h>
#include <cuda_fp16.h>
#include <cstdint>
#include <math.h>

#define N_TOK 4096
#define DIM   2048
#define FF    1024
#define NE    16
#define CAP   4096
#define CT    524288   // elements per cvt/copy tile

// half-buffer offsets (in halves)
#define OXH  0ull
#define ORG  (8ull  << 20)
#define ORW1 (40ull << 20)
#define ORW2 (72ull << 20)
#define OSG  (104ull << 20)
#define OSW1 (108ull << 20)
#define OSW2 (112ull << 20)

__device__ int    g_cnt[NE];
__device__ int    g_list[NE * CAP];
__device__ float  g_wt[NE * CAP];
__device__ __half g_half[116ull << 20];
__device__ __half g_hh[(size_t)NE * CAP * FF];      // routed hidden
__device__ __half g_hs[(size_t)N_TOK * 2 * FF];     // shared hidden
// flags: 0 f_x(16), 1 f_s(16), 2+e f_ruw(8), 18 f_copy(16), 19 f_sw2(8),
//        20+e f_rw2(4), 36 router(32), 40+mt upcnt_s(32), 72+e*32+mt upcnt_r(16)
__device__ int    g_flags[640];

// ---------- helpers ----------
__device__ __forceinline__ uint32_t smem_u32(const void* p) {
    uint32_t a;
    asm("{ .reg .u64 t; cvta.to.shared.u64 t, %1; cvt.u32.u64 %0, t; }" : "=r"(a) : "l"(p));
    return a;
}
__device__ __forceinline__ void cp16(uint32_t dst, const void* src) {
    asm volatile("cp.async.cg.shared.global [%0], [%1], 16;" :: "r"(dst), "l"(src));
}
__device__ __forceinline__ void ldm4(uint32_t* r, uint32_t a) {
    asm volatile("ldmatrix.sync.aligned.m8n8.x4.shared.b16 {%0,%1,%2,%3}, [%4];"
                 : "=r"(r[0]), "=r"(r[1]), "=r"(r[2]), "=r"(r[3]) : "r"(a));
}
__device__ __forceinline__ void ldm4t(uint32_t* r, uint32_t a) {
    asm volatile("ldmatrix.sync.aligned.m8n8.x4.trans.shared.b16 {%0,%1,%2,%3}, [%4];"
                 : "=r"(r[0]), "=r"(r[1]), "=r"(r[2]), "=r"(r[3]) : "r"(a));
}
__device__ __forceinline__ void mma16(float* d, const uint32_t* a, uint32_t b0, uint32_t b1) {
    asm volatile("mma.sync.aligned.m16n8k16.row.col.f32.f16.f16.f32 "
                 "{%0,%1,%2,%3},{%4,%5,%6,%7},{%8,%9},{%0,%1,%2,%3};"
                 : "+f"(d[0]), "+f"(d[1]), "+f"(d[2]), "+f"(d[3])
                 : "r"(a[0]), "r"(a[1]), "r"(a[2]), "r"(a[3]), "r"(b0), "r"(b1));
}
__device__ __forceinline__ float gelu_exact(float v) {
    return 0.5f * v * (1.0f + erff(v * 0.70710678118654752440f));
}
#define COMMIT() asm volatile("cp.async.commit_group;" ::: "memory")
#define WAIT1()  asm volatile("cp.async.wait_group 1;" ::: "memory")

// ---------- flag protocol ----------
__device__ __forceinline__ void bump(int* f) {
    __syncthreads();
    if (threadIdx.x == 0) { __threadfence(); atomicAdd(f, 1); }
}
__device__ __forceinline__ void waitflag(int* f, int tgt) {
    if (threadIdx.x == 0) {
        while (atomicAdd(f, 0) < tgt) __nanosleep(64);
    }
    __syncthreads();
    __threadfence();
}

// ---------- cvt / copy tiles ----------
__device__ __forceinline__ void cvt4(const float* s, size_t si, size_t dofs) {
    float4 v = *(const float4*)(s + si);
    __half2* d = (__half2*)(g_half + dofs + si);
    d[0] = __floats2half2_rn(v.x, v.y);
    d[1] = __floats2half2_rn(v.z, v.w);
}
__device__ __forceinline__ void cvt_tile(const float* s, size_t dofs, int t, int* flag) {
    size_t base = (size_t)t * CT + threadIdx.x * 4;
    for (size_t i = 0; i < CT / 512; i++) cvt4(s, base + i * 512, dofs);
    bump(flag);
}
__device__ __forceinline__ void copy_tile(const float* s, float* d, int t, int* flag) {
    size_t base = (size_t)t * CT + threadIdx.x * 4;
    for (size_t i = 0; i < CT / 512; i++)
        *(float4*)(d + base + i * 512) = *(const float4*)(s + base + i * 512);
    bump(flag);
}

// ---------- router tile: 128 tokens ----------
__device__ __forceinline__ void router_tile(const float* x, const float* wa, int t0,
                                            int wid, int lane) {
    for (int t = t0 + wid; t < t0 + 128; t += 4) {
        float acc[NE];
#pragma unroll
        for (int e = 0; e < NE; e++) acc[e] = 0.0f;
        const float* xr = x + (size_t)t * DIM;
        for (int d = lane; d < DIM; d += 32) {
            float xv = xr[d];
#pragma unroll
            for (int e = 0; e < NE; e++) acc[e] += xv * wa[(size_t)d * NE + e];
        }
#pragma unroll
        for (int e = 0; e < NE; e++)
#pragma unroll
            for (int o = 16; o > 0; o >>= 1) acc[e] += __shfl_xor_sync(0xffffffffu, acc[e], o);
        if (lane == 0) {
            float aff[NE];
#pragma unroll
            for (int e = 0; e < NE; e++) aff[e] = 1.0f / (1.0f + expf(-acc[e]));
            int e1 = 0; float p1 = aff[0];
#pragma unroll
            for (int e = 1; e < NE; e++) if (aff[e] > p1) { p1 = aff[e]; e1 = e; }
            int e2 = (e1 == 0) ? 1 : 0; float p2 = aff[e2];
#pragma unroll
            for (int e = 0; e < NE; e++) if (e != e1 && aff[e] > p2) { p2 = aff[e]; e2 = e; }
            float inv = 1.0f / (p1 + p2);
            int q1 = atomicAdd(&g_cnt[e1], 1);
            g_list[e1 * CAP + q1] = t; g_wt[e1 * CAP + q1] = p1 * inv;
            int q2 = atomicAdd(&g_cnt[e2], 1);
            g_list[e2 * CAP + q2] = t; g_wt[e2 * CAP + q2] = p2 * inv;
        }
    }
    bump(&g_flags[36]);
}

// ================= tile bodies (round-7 proven) =================
__device__ __forceinline__ void tile_up(
    int m0, int n0f, int rows, const int* list,
    const __half* G, const __half* W,
    const float* b0, const float* b1,
    __half* hbase, int hstride,
    uint32_t sbase, int* s_row, int tid, int wid, int lane)
{
    { int mm = m0 + tid; s_row[tid] = list ? list[mm < rows ? mm : m0] : mm; }
    __syncthreads();

    const __half* Ah = g_half + OXH;
    int rix[8];
#pragma unroll
    for (int i = 0; i < 8; i++) rix[i] = s_row[(tid >> 3) + i * 16];

    const int c = tid & 15;
    const int f0 = n0f + ((c >> 1) >> 1) * 16 + (c & 1) * 8;
    const __half* Bb = (((c >> 1) & 1) ? W : G) + f0;
    const int akseg = tid & 7, arow = tid >> 3, kroww = tid >> 4;
    const uint32_t a_dst = (uint32_t)(arow * 128 + ((akseg * 16) ^ ((arow & 7) << 4)));
    const uint32_t b_dst = (uint32_t)(16384 + kroww * 256 + ((c * 16) ^ (kroww << 4)));

#define UISSUE(k0g, buf) do { \
    uint32_t sB_ = sbase + (uint32_t)(buf) * 32768u; \
    _Pragma("unroll") \
    for (int i_ = 0; i_ < 8; i_++) { \
        cp16(sB_ + a_dst + (uint32_t)i_ * 2048u, Ah + (size_t)rix[i_] * DIM + (k0g) + akseg * 8); \
        cp16(sB_ + b_dst + (uint32_t)i_ * 2048u, Bb + (size_t)((k0g) + kroww + i_ * 8) * FF); \
    } \
} while (0)

    const int wm = wid & 1, wn = wid >> 1;
    const int m_off = wm * 64;
    uint32_t aoffc[4], axorl[4];
#pragma unroll
    for (int mi = 0; mi < 4; mi++) {
        int ar = m_off + mi * 16 + (lane & 15);
        aoffc[mi] = (uint32_t)(ar * 128);
        axorl[mi] = (uint32_t)((ar & 7) << 4);
    }
    const uint32_t akp = (uint32_t)((lane >> 4) * 16);
    const int kr0 = ((lane >> 3) & 1) * 8 + (lane & 7);
    const int noct = (lane >> 4) & 1;
    uint32_t boffc[4];
#pragma unroll
    for (int g = 0; g < 4; g++) {
        int nb = wn * 64 + g * 16;
        uint32_t nbyte = (uint32_t)((nb + noct * 8) * 2);
        boffc[g] = 16384u + (uint32_t)(kr0 * 256) + (nbyte ^ (uint32_t)((kr0 & 7) << 4));
    }

    float acc[32][4];
#pragma unroll
    for (int i = 0; i < 32; i++)
#pragma unroll
        for (int j = 0; j < 4; j++) acc[i][j] = 0.0f;

    UISSUE(0, 0);  COMMIT();
    UISSUE(64, 1); COMMIT();
    for (int it = 0; it < DIM / 64; it++) {
        WAIT1();
        __syncthreads();
        if (it + 2 < DIM / 64) UISSUE((it + 2) * 64, (it + 2) % 3);
        COMMIT();
        const uint32_t sb = sbase + (uint32_t)(it % 3) * 32768u;
#pragma unroll
        for (int ks = 0; ks < 4; ks++) {
            uint32_t af[4][4];
#pragma unroll
            for (int mi = 0; mi < 4; mi++)
                ldm4(af[mi], sb + aoffc[mi] + (((uint32_t)(ks * 32) + akp) ^ axorl[mi]));
            uint32_t bf[4][4];
#pragma unroll
            for (int g = 0; g < 4; g++)
                ldm4t(bf[g], sb + boffc[g] + (uint32_t)(ks * 4096));
#pragma unroll
            for (int mi = 0; mi < 4; mi++)
#pragma unroll
                for (int nt = 0; nt < 8; nt++)
                    mma16(acc[mi * 8 + nt], af[mi],
                          bf[nt >> 1][(nt & 1) * 2], bf[nt >> 1][(nt & 1) * 2 + 1]);
        }
    }
#undef UISSUE

    const int rbase = lane >> 2;
    const int cbase = (lane & 3) * 2;
#pragma unroll
    for (int mi = 0; mi < 4; mi++) {
#pragma unroll
        for (int h = 0; h < 2; h++) {
            const int m = m0 + m_off + mi * 16 + rbase + h * 8;
            if (m >= rows) continue;
#pragma unroll
            for (int gi = 0; gi < 4; gi++) {
                const int g = (gi & 1) + (gi >> 1) * 4;  // 0,1,4,5
                const int f = n0f + wn * 32 + (g >> 2) * 16 + (g & 1) * 8 + cbase;
                float c1a = acc[mi * 8 + g][h * 2 + 0] + b0[f];
                float c1b = acc[mi * 8 + g][h * 2 + 1] + b0[f + 1];
                float c2a = acc[mi * 8 + g + 2][h * 2 + 0] + b1[f];
                float c2b = acc[mi * 8 + g + 2][h * 2 + 1] + b1[f + 1];
                __half2 hv = __floats2half2_rn(gelu_exact(c1a) * c2a, gelu_exact(c1b) * c2b);
                *(__half2*)(hbase + (size_t)m * hstride + f) = hv;
            }
        }
    }
}

__device__ __forceinline__ void tile_down(
    int m0, int n0f, int rows, int kt,
    const __half* Ah, int lda,
    const int* list, const float* wtp,
    const __half* B, const float* b2, const float* b2b,
    float* outp,
    uint32_t sbase, int* s_row, int tid, int wid, int lane)
{
    s_row[tid] = m0 + tid;
    __syncthreads();

    int rix[8];
#pragma unroll
    for (int i = 0; i < 8; i++) rix[i] = s_row[(tid >> 3) + i * 16];

    const int c = tid & 15;
    const __half* Bb = B + n0f + c * 8;
    const int akseg = tid & 7, arow = tid >> 3, kroww = tid >> 4;
    const uint32_t a_dst = (uint32_t)(arow * 128 + ((akseg * 16) ^ ((arow & 7) << 4)));
    const uint32_t b_dst = (uint32_t)(16384 + kroww * 256 + ((c * 16) ^ (kroww << 4)));

#define DISSUE(k0g, buf) do { \
    uint32_t sB_ = sbase + (uint32_t)(buf) * 32768u; \
    _Pragma("unroll") \
    for (int i_ = 0; i_ < 8; i_++) { \
        cp16(sB_ + a_dst + (uint32_t)i_ * 2048u, Ah + (size_t)rix[i_] * lda + (k0g) + akseg * 8); \
        cp16(sB_ + b_dst + (uint32_t)i_ * 2048u, Bb + (size_t)((k0g) + kroww + i_ * 8) * DIM); \
    } \
} while (0)

    const int wm = wid & 1, wn = wid >> 1;
    const int m_off = wm * 64;
    uint32_t aoffc[4], axorl[4];
#pragma unroll
    for (int mi = 0; mi < 4; mi++) {
        int ar = m_off + mi * 16 + (lane & 15);
        aoffc[mi] = (uint32_t)(ar * 128);
        axorl[mi] = (uint32_t)((ar & 7) << 4);
    }
    const uint32_t akp = (uint32_t)((lane >> 4) * 16);
    const int kr0 = ((lane >> 3) & 1) * 8 + (lane & 7);
    const int noct = (lane >> 4) & 1;
    uint32_t boffc[4];
#pragma unroll
    for (int g = 0; g < 4; g++) {
        int nb = wn * 64 + g * 16;
        uint32_t nbyte = (uint32_t)((nb + noct * 8) * 2);
        boffc[g] = 16384u + (uint32_t)(kr0 * 256) + (nbyte ^ (uint32_t)((kr0 & 7) << 4));
    }

    float acc[32][4];
#pragma unroll
    for (int i = 0; i < 32; i++)
#pragma unroll
        for (int j = 0; j < 4; j++) acc[i][j] = 0.0f;

    const int NCH = kt / 64;
    DISSUE(0, 0);  COMMIT();
    DISSUE(64, 1); COMMIT();
    for (int it = 0; it < NCH; it++) {
        WAIT1();
        __syncthreads();
        if (it + 2 < NCH) DISSUE((it + 2) * 64, (it + 2) % 3);
        COMMIT();
        const uint32_t sb = sbase + (uint32_t)(it % 3) * 32768u;
#pragma unroll
        for (int ks = 0; ks < 4; ks++) {
            uint32_t af[4][4];
#pragma unroll
            for (int mi = 0; mi < 4; mi++)
                ldm4(af[mi], sb + aoffc[mi] + (((uint32_t)(ks * 32) + akp) ^ axorl[mi]));
            uint32_t bf[4][4];
#pragma unroll
            for (int g = 0; g < 4; g++)
                ldm4t(bf[g], sb + boffc[g] + (uint32_t)(ks * 4096));
#pragma unroll
            for (int mi = 0; mi < 4; mi++)
#pragma unroll
                for (int nt = 0; nt < 8; nt++)
                    mma16(acc[mi * 8 + nt], af[mi],
                          bf[nt >> 1][(nt & 1) * 2], bf[nt >> 1][(nt & 1) * 2 + 1]);
        }
    }
#undef DISSUE

    const int rbase = lane >> 2;
    const int cbase = (lane & 3) * 2;
#pragma unroll
    for (int mi = 0; mi < 4; mi++) {
#pragma unroll
        for (int h = 0; h < 2; h++) {
            const int m = m0 + m_off + mi * 16 + rbase + h * 8;
            if (m >= rows) continue;
            int tok; float w;
            if (list) { tok = list[m]; w = wtp[m]; }
            else      { tok = m; w = 1.0f; }
            float* orow = outp + (size_t)tok * DIM;
#pragma unroll
            for (int nt = 0; nt < 8; nt++) {
                const int d = n0f + wn * 64 + nt * 8 + cbase;
                float bb0 = b2[d]     + (b2b ? b2b[d]     : 0.0f);
                float bb1 = b2[d + 1] + (b2b ? b2b[d + 1] : 0.0f);
                atomicAdd(orow + d,     w * (acc[mi * 8 + nt][h * 2 + 0] + bb0));
                atomicAdd(orow + d + 1, w * (acc[mi * 8 + nt][h * 2 + 1] + bb1));
            }
        }
    }
}

// ================= fused persistent driver =================
#define GRID_P 304
// queue: [0,248) cvt/copy, [248,280) router, [280,1304) up-shared,
//        [1304,9496) up-routed, [9496,10008) down-shared, [10008,18200) down-routed

__global__ void __launch_bounds__(128, 2) moe_persist(
    const float* __restrict__ x,   const float* __restrict__ wa,
    const float* __restrict__ rg,  const float* __restrict__ rgb,
    const float* __restrict__ rw1, const float* __restrict__ rb1,
    const float* __restrict__ rw2, const float* __restrict__ rb2,
    const float* __restrict__ sg,  const float* __restrict__ sgb,
    const float* __restrict__ sw1, const float* __restrict__ sb1,
    const float* __restrict__ sw2, const float* __restrict__ sb2,
    float* __restrict__ outp)
{
    extern __shared__ char dynsm[];
    __shared__ int s_row[128];
    const int tid = threadIdx.x, wid = tid >> 5, lane = tid & 31;
    const uint32_t sbase = smem_u32(dynsm);

    for (int idx = blockIdx.x; idx < 18200; idx += gridDim.x) {
        if (idx < 248) {
            // ---- section A: cvt / copy ----
            if (idx < 16)       cvt_tile(x,   OXH,  idx,       &g_flags[0]);
            else if (idx < 24)  cvt_tile(sg,  OSG,  idx - 16,  &g_flags[1]);
            else if (idx < 32)  cvt_tile(sw1, OSW1, idx - 24,  &g_flags[1]);
            else if (idx < 160) {
                int i = idx - 32, e = i >> 3, j = i & 7;
                if (j < 4) cvt_tile(rg,  ORG,  e * 4 + j,       &g_flags[2 + e]);
                else       cvt_tile(rw1, ORW1, e * 4 + (j - 4), &g_flags[2 + e]);
            }
            else if (idx < 176) copy_tile(x, outp, idx - 160, &g_flags[18]);
            else if (idx < 184) cvt_tile(sw2, OSW2, idx - 176, &g_flags[19]);
            else {
                int i = idx - 184, e = i >> 2, j = i & 3;
                cvt_tile(rw2, ORW2, e * 4 + j, &g_flags[20 + e]);
            }
        } else if (idx < 280) {
            // ---- section B: router ----
            router_tile(x, wa, (idx - 248) * 128, wid, lane);
        } else if (idx < 1304) {
            // ---- section C1: up-shared ----
            waitflag(&g_flags[0], 16);
            waitflag(&g_flags[1], 16);
            int i = idx - 280, e = i >> 9, rem = i & 511, mt = rem >> 4, nt = rem & 15;
            tile_up(mt * 128, nt * 64, N_TOK, nullptr,
                    g_half + OSG  + (size_t)e * DIM * FF,
                    g_half + OSW1 + (size_t)e * DIM * FF,
                    sgb + (size_t)e * FF, sb1 + (size_t)e * FF,
                    g_hs + (size_t)e * FF, 2 * FF,
                    sbase, s_row, tid, wid, lane);
            bump(&g_flags[40 + mt]);
        } else if (idx < 9496) {
            // ---- section C2: up-routed ----
            int i = idx - 1304, e = i >> 9, rem = i & 511, mt = rem >> 4, nt = rem & 15;
            waitflag(&g_flags[0], 16);
            waitflag(&g_flags[2 + e], 8);
            waitflag(&g_flags[36], 32);
            int rows = g_cnt[e];
            if (mt * 128 < rows) {
                tile_up(mt * 128, nt * 64, rows, g_list + e * CAP,
                        g_half + ORG  + (size_t)e * DIM * FF,
                        g_half + ORW1 + (size_t)e * DIM * FF,
                        rgb + (size_t)e * FF, rb1 + (size_t)e * FF,
                        g_hh + (size_t)e * CAP * FF, FF,
                        sbase, s_row, tid, wid, lane);
                bump(&g_flags[72 + e * 32 + mt]);
            }
        } else if (idx < 10008) {
            // ---- section D1: down-shared ----
            int i = idx - 9496, mt = i >> 4, nt = i & 15;
            waitflag(&g_flags[18], 16);
            waitflag(&g_flags[19], 8);
            waitflag(&g_flags[40 + mt], 32);
            tile_down(mt * 128, nt * 128, N_TOK, 2 * FF,
                      g_hs, 2 * FF, nullptr, nullptr,
                      g_half + OSW2, sb2, sb2 + DIM, outp,
                      sbase, s_row, tid, wid, lane);
        } else {
            // ---- section D2: down-routed ----
            int i = idx - 10008, e = i >> 9, rem = i & 511, mt = rem >> 5, nt = rem & 15;
            // NOTE: 512 slots per expert = 32 mt x 16 nt
            mt = (rem >> 4) & 31;  // rem in [0,512): mt = rem/16
            waitflag(&g_flags[18], 16);
            waitflag(&g_flags[20 + e], 4);
            waitflag(&g_flags[36], 32);
            int rows = g_cnt[e];
            if (mt * 128 < rows) {
                waitflag(&g_flags[72 + e * 32 + mt], 16);
                tile_down(mt * 128, nt * 128, rows, FF,
                          g_hh + (size_t)e * CAP * FF, FF,
                          g_list + e * CAP, g_wt + e * CAP,
                          g_half + ORW2 + (size_t)e * FF * DIM,
                          rb2 + (size_t)e * DIM, nullptr, outp,
                          sbase, s_row, tid, wid, lane);
            }
        }
    }
}

// ---------- init ----------
__global__ void zero_flags_kernel() {
    for (int i = threadIdx.x; i < 640; i += 256) g_flags[i] = 0;
    if (threadIdx.x < NE) g_cnt[threadIdx.x] = 0;
}

// ---------- launch ----------
extern "C" void kernel_launch(void* const* d_in, const int* in_sizes, int n_in,
                              void* d_out, int out_size) {
    const float* x   = (const float*)d_in[0];
    const float* wa  = (const float*)d_in[1];
    const float* rg  = (const float*)d_in[2];
    const float* rgb = (const float*)d_in[3];
    const float* rw1 = (const float*)d_in[4];
    const float* rb1 = (const float*)d_in[5];
    const float* rw2 = (const float*)d_in[6];
    const float* rb2 = (const float*)d_in[7];
    const float* sg  = (const float*)d_in[8];
    const float* sgb = (const float*)d_in[9];
    const float* sw1 = (const float*)d_in[10];
    const float* sb1 = (const float*)d_in[11];
    const float* sw2 = (const float*)d_in[12];
    const float* sb2 = (const float*)d_in[13];
    float* out = (float*)d_out;

    const int smem = 3 * 32768;
    cudaFuncSetAttribute(moe_persist, cudaFuncAttributeMaxDynamicSharedMemorySize, smem);

    zero_flags_kernel<<<1, 256>>>();
    moe_persist<<<GRID_P, 128, smem>>>(x, wa, rg, rgb, rw1, rb1, rw2, rb2,
                                       sg, sgb, sw1, sb1, sw2, sb2, out);
}

// round 11
// speedup vs baseline: 1.8268x; 1.8268x over previous
#include <cuda_runtime.h>
#include <cuda_fp16.h>
#include <cstdint>
#include <math.h>

#define N_TOK 4096
#define DIM   2048
#define FF    1024
#define NE    16
#define CAP   4096

// half-buffer offsets (in halves)
#define OXH  0ull
#define ORG  (8ull  << 20)
#define ORW1 (40ull << 20)
#define ORW2 (72ull << 20)
#define OSG  (104ull << 20)
#define OSW1 (108ull << 20)
#define OSW2 (112ull << 20)

__device__ int    g_cnt[NE];
__device__ int    g_list[NE * CAP];
__device__ float  g_wt[NE * CAP];
__device__ __half g_half[116ull << 20];
__device__ __half g_hh[(size_t)NE * CAP * FF];    // routed hidden ONLY
__device__ __half g_hs[(size_t)N_TOK * 2 * FF];   // shared hidden (no aliasing)

// ---------- helpers ----------
__device__ __forceinline__ uint32_t smem_u32(const void* p) {
    uint32_t a;
    asm("{ .reg .u64 t; cvta.to.shared.u64 t, %1; cvt.u32.u64 %0, t; }" : "=r"(a) : "l"(p));
    return a;
}
__device__ __forceinline__ void cp16(uint32_t dst, const void* src) {
    asm volatile("cp.async.cg.shared.global [%0], [%1], 16;" :: "r"(dst), "l"(src));
}
__device__ __forceinline__ void ldm4(uint32_t* r, uint32_t a) {
    asm volatile("ldmatrix.sync.aligned.m8n8.x4.shared.b16 {%0,%1,%2,%3}, [%4];"
                 : "=r"(r[0]), "=r"(r[1]), "=r"(r[2]), "=r"(r[3]) : "r"(a));
}
__device__ __forceinline__ void ldm4t(uint32_t* r, uint32_t a) {
    asm volatile("ldmatrix.sync.aligned.m8n8.x4.trans.shared.b16 {%0,%1,%2,%3}, [%4];"
                 : "=r"(r[0]), "=r"(r[1]), "=r"(r[2]), "=r"(r[3]) : "r"(a));
}
__device__ __forceinline__ void mma16(float* d, const uint32_t* a, uint32_t b0, uint32_t b1) {
    asm volatile("mma.sync.aligned.m16n8k16.row.col.f32.f16.f16.f32 "
                 "{%0,%1,%2,%3},{%4,%5,%6,%7},{%8,%9},{%0,%1,%2,%3};"
                 : "+f"(d[0]), "+f"(d[1]), "+f"(d[2]), "+f"(d[3])
                 : "r"(a[0]), "r"(a[1]), "r"(a[2]), "r"(a[3]), "r"(b0), "r"(b1));
}
__device__ __forceinline__ float gelu_exact(float v) {
    return 0.5f * v * (1.0f + erff(v * 0.70710678118654752440f));
}
#define COMMIT() asm volatile("cp.async.commit_group;" ::: "memory")
#define WAIT1()  asm volatile("cp.async.wait_group 1;" ::: "memory")

// ---------- merged conversions ----------
__device__ __forceinline__ void cvt4(const float* s, size_t si, size_t dofs) {
    float4 v = *(const float4*)(s + si);
    __half2* d = (__half2*)(g_half + dofs + si);
    d[0] = __floats2half2_rn(v.x, v.y);
    d[1] = __floats2half2_rn(v.z, v.w);
}
__global__ void cvt_up_kernel(const float* __restrict__ x, const float* __restrict__ rg,
                              const float* __restrict__ rw1, const float* __restrict__ sg,
                              const float* __restrict__ sw1) {
    const size_t NX = 8388608ull, NR = 33554432ull, NS = 4194304ull;
    size_t i = ((size_t)blockIdx.x * 256 + threadIdx.x) * 4;
    if (i < NX) { cvt4(x, i, OXH); return; }
    i -= NX;
    if (i < NR) { cvt4(rg, i, ORG); return; }
    i -= NR;
    if (i < NR) { cvt4(rw1, i, ORW1); return; }
    i -= NR;
    if (i < NS) { cvt4(sg, i, OSG); return; }
    i -= NS;
    cvt4(sw1, i, OSW1);
}
__global__ void cvt_dn_kernel(const float* __restrict__ rw2, const float* __restrict__ sw2) {
    const size_t NR = 33554432ull;
    size_t i = ((size_t)blockIdx.x * 256 + threadIdx.x) * 4;
    if (i < NR) { cvt4(rw2, i, ORW2); return; }
    i -= NR;
    cvt4(sw2, i, OSW2);
}

// ---------- router ----------
__global__ void zero_cnt_kernel() { if (threadIdx.x < NE) g_cnt[threadIdx.x] = 0; }

__global__ void router_kernel(const float* __restrict__ x, const float* __restrict__ wa) {
    int t = (blockIdx.x * blockDim.x + threadIdx.x) >> 5;
    int lane = threadIdx.x & 31;
    if (t >= N_TOK) return;
    float acc[NE];
#pragma unroll
    for (int e = 0; e < NE; e++) acc[e] = 0.0f;
    const float* xr = x + (size_t)t * DIM;
    for (int d = lane; d < DIM; d += 32) {
        float xv = xr[d];
#pragma unroll
        for (int e = 0; e < NE; e++) acc[e] += xv * wa[(size_t)d * NE + e];
    }
#pragma unroll
    for (int e = 0; e < NE; e++)
#pragma unroll
        for (int o = 16; o > 0; o >>= 1) acc[e] += __shfl_xor_sync(0xffffffffu, acc[e], o);
    if (lane == 0) {
        float aff[NE];
#pragma unroll
        for (int e = 0; e < NE; e++) aff[e] = 1.0f / (1.0f + expf(-acc[e]));
        int e1 = 0; float p1 = aff[0];
#pragma unroll
        for (int e = 1; e < NE; e++) if (aff[e] > p1) { p1 = aff[e]; e1 = e; }
        int e2 = (e1 == 0) ? 1 : 0; float p2 = aff[e2];
#pragma unroll
        for (int e = 0; e < NE; e++) if (e != e1 && aff[e] > p2) { p2 = aff[e]; e2 = e; }
        float inv = 1.0f / (p1 + p2);
        int q1 = atomicAdd(&g_cnt[e1], 1);
        g_list[e1 * CAP + q1] = t; g_wt[e1 * CAP + q1] = p1 * inv;
        int q2 = atomicAdd(&g_cnt[e2], 1);
        g_list[e2 * CAP + q2] = t; g_wt[e2 * CAP + q2] = p2 * inv;
    }
}

// ---------- fp16 warp-MMA GEMM: 128x128 CTA, 4 warps of 64x64 ----------
// modes: 0 up-shared (writes g_hs), 1 up-routed (writes g_hh),
//        2 down-shared (reads g_hs), 3 down-routed (reads g_hh)
template <int MODE>
__global__ void __launch_bounds__(128, 2) mma_kernel(
    const float* __restrict__ bias0, const float* __restrict__ bias1,
    const float* __restrict__ xres, float* __restrict__ outp)
{
    constexpr bool UP = (MODE <= 1);
    constexpr int KT  = (MODE == 3) ? FF : DIM;
    constexpr int LDA = (MODE == 3) ? FF : DIM;   // MODE2: g_hs row = 2*FF = 2048 = DIM
    constexpr int LDB = UP ? FF : DIM;
    constexpr int NCH = KT / 64;

    const int e = blockIdx.z;
    const int rows = (MODE == 1 || MODE == 3) ? g_cnt[e] : N_TOK;
    const int m0 = blockIdx.x * 128;
    if (m0 >= rows) return;
    const int n0f = blockIdx.y * (UP ? 64 : 128);

    extern __shared__ char dynsm[];
    __shared__ int s_row[128];
    const int tid = threadIdx.x, wid = tid >> 5, lane = tid & 31;
    const uint32_t sbase = smem_u32(dynsm);

    {
        int mm = m0 + tid;
        s_row[tid] = (MODE == 1) ? g_list[e * CAP + (mm < rows ? mm : m0)] : mm;
    }
    __syncthreads();

    const __half* Ah = UP ? (g_half + OXH)
                          : (MODE == 2 ? g_hs : g_hh + (size_t)e * CAP * FF);
    int rix[8];
#pragma unroll
    for (int i = 0; i < 8; i++) rix[i] = s_row[(tid >> 3) + i * 16];

    const int c = tid & 15;
    const __half* Bb;
    if (UP) {
        const __half* G = g_half + (MODE == 0 ? OSG : ORG) + (size_t)e * DIM * FF;
        const __half* W = g_half + (MODE == 0 ? OSW1 : ORW1) + (size_t)e * DIM * FF;
        int f = n0f + (c >> 2) * 16 + (c & 1) * 8;
        Bb = (((c >> 1) & 1) ? W : G) + f;
    } else {
        Bb = g_half + (MODE == 2 ? OSW2 : (ORW2 + (size_t)e * FF * DIM)) + n0f + c * 8;
    }
    const int akseg = tid & 7, arow = tid >> 3, kroww = tid >> 4;
    const uint32_t a_dst = (uint32_t)(arow * 128 + ((akseg * 16) ^ ((arow & 7) << 4)));
    const uint32_t b_dst = (uint32_t)(16384 + kroww * 256 + ((c * 16) ^ (kroww << 4)));

#define ISSUE(k0g, buf) do { \
    uint32_t sB_ = sbase + (uint32_t)(buf) * 32768u; \
    _Pragma("unroll") \
    for (int i_ = 0; i_ < 8; i_++) { \
        cp16(sB_ + a_dst + (uint32_t)i_ * 2048u, Ah + (size_t)rix[i_] * LDA + (k0g) + akseg * 8); \
        cp16(sB_ + b_dst + (uint32_t)i_ * 2048u, Bb + (size_t)((k0g) + kroww + i_ * 8) * LDB); \
    } \
} while (0)

    const int wm = wid & 1, wn = wid >> 1;
    const int m_off = wm * 64;
    uint32_t aoffc[4], axorl[4];
#pragma unroll
    for (int mi = 0; mi < 4; mi++) {
        int ar = m_off + mi * 16 + (lane & 15);
        aoffc[mi] = (uint32_t)(ar * 128);
        axorl[mi] = (uint32_t)((ar & 7) << 4);
    }
    const uint32_t akp = (uint32_t)((lane >> 4) * 16);
    const int kr0 = ((lane >> 3) & 1) * 8 + (lane & 7);
    const int noct = (lane >> 4) & 1;
    uint32_t boffc[4];
#pragma unroll
    for (int g = 0; g < 4; g++) {
        int nb = wn * 64 + g * 16;
        uint32_t nbyte = (uint32_t)((nb + noct * 8) * 2);
        boffc[g] = 16384u + (uint32_t)(kr0 * 256) + (nbyte ^ (uint32_t)((kr0 & 7) << 4));
    }

    float acc[32][4];
#pragma unroll
    for (int i = 0; i < 32; i++)
#pragma unroll
        for (int j = 0; j < 4; j++) acc[i][j] = 0.0f;

    ISSUE(0, 0);  COMMIT();
    ISSUE(64, 1); COMMIT();
    for (int it = 0; it < NCH; it++) {
        WAIT1();
        __syncthreads();
        if (it + 2 < NCH) ISSUE((it + 2) * 64, (it + 2) % 3);
        COMMIT();
        const uint32_t sb = sbase + (uint32_t)(it % 3) * 32768u;
#pragma unroll
        for (int ks = 0; ks < 4; ks++) {
            uint32_t af[4][4];
#pragma unroll
            for (int mi = 0; mi < 4; mi++)
                ldm4(af[mi], sb + aoffc[mi] + (((uint32_t)(ks * 32) + akp) ^ axorl[mi]));
            uint32_t bf[4][4];
#pragma unroll
            for (int g = 0; g < 4; g++)
                ldm4t(bf[g], sb + boffc[g] + (uint32_t)(ks * 4096));
#pragma unroll
            for (int mi = 0; mi < 4; mi++)
#pragma unroll
                for (int nt = 0; nt < 8; nt++)
                    mma16(acc[mi * 8 + nt], af[mi],
                          bf[nt >> 1][(nt & 1) * 2], bf[nt >> 1][(nt & 1) * 2 + 1]);
        }
    }
#undef ISSUE

    const int rbase = lane >> 2;
    const int cbase = (lane & 3) * 2;
    if (UP) {
#pragma unroll
        for (int mi = 0; mi < 4; mi++) {
#pragma unroll
            for (int h = 0; h < 2; h++) {
                const int m = m0 + m_off + mi * 16 + rbase + h * 8;
                if (m >= rows) continue;
#pragma unroll
                for (int gi = 0; gi < 4; gi++) {
                    const int g = (gi & 1) + (gi >> 1) * 4;  // 0,1,4,5
                    const int f = n0f + wn * 32 + (g >> 2) * 16 + (g & 1) * 8 + cbase;
                    float c1a = acc[mi * 8 + g][h * 2 + 0] + bias0[(size_t)e * FF + f];
                    float c1b = acc[mi * 8 + g][h * 2 + 1] + bias0[(size_t)e * FF + f + 1];
                    float c2a = acc[mi * 8 + g + 2][h * 2 + 0] + bias1[(size_t)e * FF + f];
                    float c2b = acc[mi * 8 + g + 2][h * 2 + 1] + bias1[(size_t)e * FF + f + 1];
                    __half2 hv = __floats2half2_rn(gelu_exact(c1a) * c2a, gelu_exact(c1b) * c2b);
                    __half* dst = (MODE == 0)
                        ? (g_hs + (size_t)m * (2 * FF) + (size_t)e * FF + f)
                        : (g_hh + ((size_t)e * CAP + m) * FF + f);
                    *(__half2*)dst = hv;
                }
            }
        }
    } else {
#pragma unroll
        for (int mi = 0; mi < 4; mi++) {
#pragma unroll
            for (int h = 0; h < 2; h++) {
                const int m = m0 + m_off + mi * 16 + rbase + h * 8;
                if (m >= rows) continue;
                int tok = 0; float w = 0.0f;
                if (MODE == 3) { tok = g_list[e * CAP + m]; w = g_wt[e * CAP + m]; }
#pragma unroll
                for (int nt = 0; nt < 8; nt++) {
                    const int d = n0f + wn * 64 + nt * 8 + cbase;
                    float v0 = acc[mi * 8 + nt][h * 2 + 0];
                    float v1 = acc[mi * 8 + nt][h * 2 + 1];
                    if (MODE == 2) {
                        size_t o = (size_t)m * DIM + d;
                        float2 xv = *(const float2*)(xres + o);
                        float2 ov = make_float2(
                            xv.x + v0 + bias0[d] + bias0[DIM + d],
                            xv.y + v1 + bias0[d + 1] + bias0[DIM + d + 1]);
                        *(float2*)(outp + o) = ov;
                    } else {
                        float* dst = outp + (size_t)tok * DIM + d;
                        atomicAdd(dst + 0, w * (v0 + bias0[(size_t)e * DIM + d]));
                        atomicAdd(dst + 1, w * (v1 + bias0[(size_t)e * DIM + d + 1]));
                    }
                }
            }
        }
    }
}

// ---------- launch: graph-DAG overlap via forked streams ----------
extern "C" void kernel_launch(void* const* d_in, const int* in_sizes, int n_in,
                              void* d_out, int out_size) {
    const float* x   = (const float*)d_in[0];
    const float* wa  = (const float*)d_in[1];
    const float* rg  = (const float*)d_in[2];
    const float* rgb = (const float*)d_in[3];
    const float* rw1 = (const float*)d_in[4];
    const float* rb1 = (const float*)d_in[5];
    const float* rw2 = (const float*)d_in[6];
    const float* rb2 = (const float*)d_in[7];
    const float* sg  = (const float*)d_in[8];
    const float* sgb = (const float*)d_in[9];
    const float* sw1 = (const float*)d_in[10];
    const float* sb1 = (const float*)d_in[11];
    const float* sw2 = (const float*)d_in[12];
    const float* sb2 = (const float*)d_in[13];
    float* out = (float*)d_out;

    static cudaStream_t s1 = nullptr, s2 = nullptr;
    static cudaEvent_t evF = nullptr, ev1 = nullptr, ev2 = nullptr;
    static bool attr_done = false;
    if (!s1) {
        cudaStreamCreateWithFlags(&s1, cudaStreamNonBlocking);
        cudaStreamCreateWithFlags(&s2, cudaStreamNonBlocking);
        cudaEventCreateWithFlags(&evF, cudaEventDisableTiming);
        cudaEventCreateWithFlags(&ev1, cudaEventDisableTiming);
        cudaEventCreateWithFlags(&ev2, cudaEventDisableTiming);
    }
    const int smem = 3 * 32768;
    if (!attr_done) {
        cudaFuncSetAttribute(mma_kernel<0>, cudaFuncAttributeMaxDynamicSharedMemorySize, smem);
        cudaFuncSetAttribute(mma_kernel<1>, cudaFuncAttributeMaxDynamicSharedMemorySize, smem);
        cudaFuncSetAttribute(mma_kernel<2>, cudaFuncAttributeMaxDynamicSharedMemorySize, smem);
        cudaFuncSetAttribute(mma_kernel<3>, cudaFuncAttributeMaxDynamicSharedMemorySize, smem);
        attr_done = true;
    }

    // fork side streams off the main (capture) stream
    cudaEventRecord(evF, 0);
    cudaStreamWaitEvent(s1, evF, 0);
    cudaStreamWaitEvent(s2, evF, 0);

    // s1: conversions needed by the up phase
    cvt_up_kernel<<<(8388608 + 2 * 33554432 + 2 * 4194304) / 1024, 256, 0, s1>>>(x, rg, rw1, sg, sw1);
    cudaEventRecord(ev1, s1);
    // s2: conversions needed by the down phase (overlaps router + up GEMMs)
    cvt_dn_kernel<<<(33554432 + 4194304) / 1024, 256, 0, s2>>>(rw2, sw2);
    cudaEventRecord(ev2, s2);

    // main stream: router (independent of conversions)
    zero_cnt_kernel<<<1, 32>>>();
    router_kernel<<<N_TOK / 4, 128>>>(x, wa);

    // join cvt_up, then up GEMMs (g_hs and g_hh are disjoint — order within up phase free)
    cudaStreamWaitEvent(0, ev1, 0);
    mma_kernel<0><<<dim3(N_TOK / 128, FF / 64, 2), 128, smem>>>(sgb, sb1, nullptr, nullptr);
    mma_kernel<1><<<dim3(CAP / 128, FF / 64, NE), 128, smem>>>(rgb, rb1, nullptr, nullptr);

    // join cvt_dn, then down GEMMs (shared writes out=x+..., routed atomically adds)
    cudaStreamWaitEvent(0, ev2, 0);
    mma_kernel<2><<<dim3(N_TOK / 128, DIM / 128, 1), 128, smem>>>(sb2, nullptr, x, out);
    mma_kernel<3><<<dim3(CAP / 128, DIM / 128, NE), 128, smem>>>(rb2, nullptr, nullptr, out);
}

// round 12
// speedup vs baseline: 2.8317x; 1.5501x over previous
#include <cuda_runtime.h>
#include <cuda_fp16.h>
#include <cstdint>
#include <math.h>

#define N_TOK 4096
#define DIM   2048
#define FF    1024
#define NE    16
#define CAP   4096

// half-buffer offsets (in halves)
#define OXH  0ull
#define ORG  (8ull  << 20)
#define ORW1 (40ull << 20)
#define ORW2 (72ull << 20)
#define OSG  (104ull << 20)
#define OSW1 (108ull << 20)
#define OSW2 (112ull << 20)

__device__ int    g_cnt[NE];
__device__ int    g_list[NE * CAP];
__device__ float  g_wt[NE * CAP];
__device__ __half g_half[116ull << 20];
__device__ __half g_hh[(size_t)NE * CAP * FF];    // routed hidden
__device__ __half g_hs[(size_t)N_TOK * 2 * FF];   // shared hidden

// ---------- helpers ----------
__device__ __forceinline__ uint32_t smem_u32(const void* p) {
    uint32_t a;
    asm("{ .reg .u64 t; cvta.to.shared.u64 t, %1; cvt.u32.u64 %0, t; }" : "=r"(a) : "l"(p));
    return a;
}
__device__ __forceinline__ void cp16(uint32_t dst, const void* src) {
    asm volatile("cp.async.cg.shared.global [%0], [%1], 16;" :: "r"(dst), "l"(src));
}
__device__ __forceinline__ void ldm4(uint32_t* r, uint32_t a) {
    asm volatile("ldmatrix.sync.aligned.m8n8.x4.shared.b16 {%0,%1,%2,%3}, [%4];"
                 : "=r"(r[0]), "=r"(r[1]), "=r"(r[2]), "=r"(r[3]) : "r"(a));
}
__device__ __forceinline__ void ldm4t(uint32_t* r, uint32_t a) {
    asm volatile("ldmatrix.sync.aligned.m8n8.x4.trans.shared.b16 {%0,%1,%2,%3}, [%4];"
                 : "=r"(r[0]), "=r"(r[1]), "=r"(r[2]), "=r"(r[3]) : "r"(a));
}
__device__ __forceinline__ void mma16(float* d, const uint32_t* a, uint32_t b0, uint32_t b1) {
    asm volatile("mma.sync.aligned.m16n8k16.row.col.f32.f16.f16.f32 "
                 "{%0,%1,%2,%3},{%4,%5,%6,%7},{%8,%9},{%0,%1,%2,%3};"
                 : "+f"(d[0]), "+f"(d[1]), "+f"(d[2]), "+f"(d[3])
                 : "r"(a[0]), "r"(a[1]), "r"(a[2]), "r"(a[3]), "r"(b0), "r"(b1));
}
__device__ __forceinline__ float gelu_exact(float v) {
    return 0.5f * v * (1.0f + erff(v * 0.70710678118654752440f));
}
#define COMMIT() asm volatile("cp.async.commit_group;" ::: "memory")
#define WAIT1()  asm volatile("cp.async.wait_group 1;" ::: "memory")

// ---------- merged conversions ----------
__device__ __forceinline__ void cvt4(const float* s, size_t si, size_t dofs) {
    float4 v = *(const float4*)(s + si);
    __half2* d = (__half2*)(g_half + dofs + si);
    d[0] = __floats2half2_rn(v.x, v.y);
    d[1] = __floats2half2_rn(v.z, v.w);
}
__global__ void cvt_up_kernel(const float* __restrict__ x, const float* __restrict__ rg,
                              const float* __restrict__ rw1, const float* __restrict__ sg,
                              const float* __restrict__ sw1) {
    const size_t NX = 8388608ull, NR = 33554432ull, NS = 4194304ull;
    size_t i = ((size_t)blockIdx.x * 256 + threadIdx.x) * 4;
    if (i < NX) { cvt4(x, i, OXH); return; }
    i -= NX;
    if (i < NR) { cvt4(rg, i, ORG); return; }
    i -= NR;
    if (i < NR) { cvt4(rw1, i, ORW1); return; }
    i -= NR;
    if (i < NS) { cvt4(sg, i, OSG); return; }
    i -= NS;
    cvt4(sw1, i, OSW1);
}
__global__ void cvt_dn_kernel(const float* __restrict__ rw2, const float* __restrict__ sw2) {
    const size_t NR = 33554432ull;
    size_t i = ((size_t)blockIdx.x * 256 + threadIdx.x) * 4;
    if (i < NR) { cvt4(rw2, i, ORW2); return; }
    i -= NR;
    cvt4(sw2, i, OSW2);
}

// ---------- router (coalesced wa, shfl-distributed x, warp top-2) ----------
__global__ void zero_cnt_kernel() { if (threadIdx.x < NE) g_cnt[threadIdx.x] = 0; }

__global__ void router_kernel(const float* __restrict__ x, const float* __restrict__ wa) {
    int t = (blockIdx.x * blockDim.x + threadIdx.x) >> 5;
    int lane = threadIdx.x & 31;
    if (t >= N_TOK) return;
    const int esub = lane & 15, dhalf = lane >> 4;

    float acc = 0.0f;
    const float* xr = x + (size_t)t * DIM;
    for (int db = 0; db < DIM; db += 32) {
        float xv = xr[db + lane];                       // coalesced
#pragma unroll
        for (int i = 0; i < 16; i++) {
            float xj = __shfl_sync(0xffffffffu, xv, 2 * i + dhalf);
            acc += xj * wa[(size_t)(db + 2 * i + dhalf) * NE + esub];  // coalesced 128B
        }
    }
    acc += __shfl_xor_sync(0xffffffffu, acc, 16);       // all lanes: full dot for e=esub
    float aff = 1.0f / (1.0f + expf(-acc));

    // top-1 with lower-index tie-break
    float v1 = aff; int i1 = esub;
#pragma unroll
    for (int m = 8; m > 0; m >>= 1) {
        float ov = __shfl_xor_sync(0xffffffffu, v1, m);
        int   oi = __shfl_xor_sync(0xffffffffu, i1, m);
        if (ov > v1 || (ov == v1 && oi < i1)) { v1 = ov; i1 = oi; }
    }
    // top-2: exclude i1
    float v2 = (esub == i1) ? -1e30f : aff; int i2 = esub;
#pragma unroll
    for (int m = 8; m > 0; m >>= 1) {
        float ov = __shfl_xor_sync(0xffffffffu, v2, m);
        int   oi = __shfl_xor_sync(0xffffffffu, i2, m);
        if (ov > v2 || (ov == v2 && oi < i2)) { v2 = ov; i2 = oi; }
    }
    if (lane == 0) {
        float inv = 1.0f / (v1 + v2);
        int q1 = atomicAdd(&g_cnt[i1], 1);
        g_list[i1 * CAP + q1] = t; g_wt[i1 * CAP + q1] = v1 * inv;
        int q2 = atomicAdd(&g_cnt[i2], 1);
        g_list[i2 * CAP + q2] = t; g_wt[i2 * CAP + q2] = v2 * inv;
    }
}

// ---------- fp16 warp-MMA GEMM: 128x128 CTA, 4 warps of 64x64 ----------
// modes: 0 up-shared (writes g_hs), 1 up-routed (writes g_hh),
//        2 down-shared (reads g_hs), 3 down-routed (reads g_hh)
template <int MODE>
__global__ void __launch_bounds__(128, 2) mma_kernel(
    const float* __restrict__ bias0, const float* __restrict__ bias1,
    const float* __restrict__ xres, float* __restrict__ outp)
{
    constexpr bool UP = (MODE <= 1);
    constexpr int KT  = (MODE == 3) ? FF : DIM;
    constexpr int LDA = (MODE == 3) ? FF : DIM;   // MODE2: g_hs row = 2*FF = DIM
    constexpr int LDB = UP ? FF : DIM;
    constexpr int NCH = KT / 64;

    const int e = blockIdx.z;
    const int rows = (MODE == 1 || MODE == 3) ? g_cnt[e] : N_TOK;
    const int m0 = blockIdx.x * 128;
    if (m0 >= rows) return;
    const int n0f = blockIdx.y * (UP ? 64 : 128);

    extern __shared__ char dynsm[];
    __shared__ int s_row[128];
    const int tid = threadIdx.x, wid = tid >> 5, lane = tid & 31;
    const uint32_t sbase = smem_u32(dynsm);

    {
        int mm = m0 + tid;
        s_row[tid] = (MODE == 1) ? g_list[e * CAP + (mm < rows ? mm : m0)] : mm;
    }
    __syncthreads();

    const __half* Ah = UP ? (g_half + OXH)
                          : (MODE == 2 ? g_hs : g_hh + (size_t)e * CAP * FF);
    int rix[8];
#pragma unroll
    for (int i = 0; i < 8; i++) rix[i] = s_row[(tid >> 3) + i * 16];

    const int c = tid & 15;
    const __half* Bb;
    if (UP) {
        const __half* G = g_half + (MODE == 0 ? OSG : ORG) + (size_t)e * DIM * FF;
        const __half* W = g_half + (MODE == 0 ? OSW1 : ORW1) + (size_t)e * DIM * FF;
        int f = n0f + (c >> 2) * 16 + (c & 1) * 8;
        Bb = (((c >> 1) & 1) ? W : G) + f;
    } else {
        Bb = g_half + (MODE == 2 ? OSW2 : (ORW2 + (size_t)e * FF * DIM)) + n0f + c * 8;
    }
    const int akseg = tid & 7, arow = tid >> 3, kroww = tid >> 4;
    const uint32_t a_dst = (uint32_t)(arow * 128 + ((akseg * 16) ^ ((arow & 7) << 4)));
    const uint32_t b_dst = (uint32_t)(16384 + kroww * 256 + ((c * 16) ^ (kroww << 4)));

#define ISSUE(k0g, buf) do { \
    uint32_t sB_ = sbase + (uint32_t)(buf) * 32768u; \
    _Pragma("unroll") \
    for (int i_ = 0; i_ < 8; i_++) { \
        cp16(sB_ + a_dst + (uint32_t)i_ * 2048u, Ah + (size_t)rix[i_] * LDA + (k0g) + akseg * 8); \
        cp16(sB_ + b_dst + (uint32_t)i_ * 2048u, Bb + (size_t)((k0g) + kroww + i_ * 8) * LDB); \
    } \
} while (0)

    const int wm = wid & 1, wn = wid >> 1;
    const int m_off = wm * 64;
    uint32_t aoffc[4], axorl[4];
#pragma unroll
    for (int mi = 0; mi < 4; mi++) {
        int ar = m_off + mi * 16 + (lane & 15);
        aoffc[mi] = (uint32_t)(ar * 128);
        axorl[mi] = (uint32_t)((ar & 7) << 4);
    }
    const uint32_t akp = (uint32_t)((lane >> 4) * 16);
    const int kr0 = ((lane >> 3) & 1) * 8 + (lane & 7);
    const int noct = (lane >> 4) & 1;
    uint32_t boffc[4];
#pragma unroll
    for (int g = 0; g < 4; g++) {
        int nb = wn * 64 + g * 16;
        uint32_t nbyte = (uint32_t)((nb + noct * 8) * 2);
        boffc[g] = 16384u + (uint32_t)(kr0 * 256) + (nbyte ^ (uint32_t)((kr0 & 7) << 4));
    }

    float acc[32][4];
#pragma unroll
    for (int i = 0; i < 32; i++)
#pragma unroll
        for (int j = 0; j < 4; j++) acc[i][j] = 0.0f;

    ISSUE(0, 0);  COMMIT();
    ISSUE(64, 1); COMMIT();
    for (int it = 0; it < NCH; it++) {
        WAIT1();
        __syncthreads();
        if (it + 2 < NCH) ISSUE((it + 2) * 64, (it + 2) % 3);
        COMMIT();
        const uint32_t sb = sbase + (uint32_t)(it % 3) * 32768u;
#pragma unroll
        for (int ks = 0; ks < 4; ks++) {
            uint32_t af[4][4];
#pragma unroll
            for (int mi = 0; mi < 4; mi++)
                ldm4(af[mi], sb + aoffc[mi] + (((uint32_t)(ks * 32) + akp) ^ axorl[mi]));
            uint32_t bf[4][4];
#pragma unroll
            for (int g = 0; g < 4; g++)
                ldm4t(bf[g], sb + boffc[g] + (uint32_t)(ks * 4096));
#pragma unroll
            for (int mi = 0; mi < 4; mi++)
#pragma unroll
                for (int nt = 0; nt < 8; nt++)
                    mma16(acc[mi * 8 + nt], af[mi],
                          bf[nt >> 1][(nt & 1) * 2], bf[nt >> 1][(nt & 1) * 2 + 1]);
        }
    }
#undef ISSUE

    const int rbase = lane >> 2;
    const int cbase = (lane & 3) * 2;
    if (UP) {
#pragma unroll
        for (int mi = 0; mi < 4; mi++) {
#pragma unroll
            for (int h = 0; h < 2; h++) {
                const int m = m0 + m_off + mi * 16 + rbase + h * 8;
                if (m >= rows) continue;
#pragma unroll
                for (int gi = 0; gi < 4; gi++) {
                    const int g = (gi & 1) + (gi >> 1) * 4;  // 0,1,4,5
                    const int f = n0f + wn * 32 + (g >> 2) * 16 + (g & 1) * 8 + cbase;
                    float c1a = acc[mi * 8 + g][h * 2 + 0] + bias0[(size_t)e * FF + f];
                    float c1b = acc[mi * 8 + g][h * 2 + 1] + bias0[(size_t)e * FF + f + 1];
                    float c2a = acc[mi * 8 + g + 2][h * 2 + 0] + bias1[(size_t)e * FF + f];
                    float c2b = acc[mi * 8 + g + 2][h * 2 + 1] + bias1[(size_t)e * FF + f + 1];
                    __half2 hv = __floats2half2_rn(gelu_exact(c1a) * c2a, gelu_exact(c1b) * c2b);
                    __half* dst = (MODE == 0)
                        ? (g_hs + (size_t)m * (2 * FF) + (size_t)e * FF + f)
                        : (g_hh + ((size_t)e * CAP + m) * FF + f);
                    *(__half2*)dst = hv;
                }
            }
        }
    } else {
#pragma unroll
        for (int mi = 0; mi < 4; mi++) {
#pragma unroll
            for (int h = 0; h < 2; h++) {
                const int m = m0 + m_off + mi * 16 + rbase + h * 8;
                if (m >= rows) continue;
                int tok = 0; float w = 0.0f;
                if (MODE == 3) { tok = g_list[e * CAP + m]; w = g_wt[e * CAP + m]; }
#pragma unroll
                for (int nt = 0; nt < 8; nt++) {
                    const int d = n0f + wn * 64 + nt * 8 + cbase;
                    float v0 = acc[mi * 8 + nt][h * 2 + 0];
                    float v1 = acc[mi * 8 + nt][h * 2 + 1];
                    if (MODE == 2) {
                        size_t o = (size_t)m * DIM + d;
                        float2 xv = *(const float2*)(xres + o);
                        float2 ov = make_float2(
                            xv.x + v0 + bias0[d] + bias0[DIM + d],
                            xv.y + v1 + bias0[d + 1] + bias0[DIM + d + 1]);
                        *(float2*)(outp + o) = ov;
                    } else {
                        float* dst = outp + (size_t)tok * DIM + d;
                        atomicAdd(dst + 0, w * (v0 + bias0[(size_t)e * DIM + d]));
                        atomicAdd(dst + 1, w * (v1 + bias0[(size_t)e * DIM + d + 1]));
                    }
                }
            }
        }
    }
}

// ---------- launch ----------
extern "C" void kernel_launch(void* const* d_in, const int* in_sizes, int n_in,
                              void* d_out, int out_size) {
    const float* x   = (const float*)d_in[0];
    const float* wa  = (const float*)d_in[1];
    const float* rg  = (const float*)d_in[2];
    const float* rgb = (const float*)d_in[3];
    const float* rw1 = (const float*)d_in[4];
    const float* rb1 = (const float*)d_in[5];
    const float* rw2 = (const float*)d_in[6];
    const float* rb2 = (const float*)d_in[7];
    const float* sg  = (const float*)d_in[8];
    const float* sgb = (const float*)d_in[9];
    const float* sw1 = (const float*)d_in[10];
    const float* sb1 = (const float*)d_in[11];
    const float* sw2 = (const float*)d_in[12];
    const float* sb2 = (const float*)d_in[13];
    float* out = (float*)d_out;

    static cudaStream_t s1 = nullptr, s2 = nullptr;
    static cudaEvent_t evF = nullptr, ev1 = nullptr, evCU = nullptr, ev2 = nullptr;
    static bool attr_done = false;
    if (!s1) {
        cudaStreamCreateWithFlags(&s1, cudaStreamNonBlocking);
        cudaStreamCreateWithFlags(&s2, cudaStreamNonBlocking);
        cudaEventCreateWithFlags(&evF, cudaEventDisableTiming);
        cudaEventCreateWithFlags(&ev1, cudaEventDisableTiming);
        cudaEventCreateWithFlags(&evCU, cudaEventDisableTiming);
        cudaEventCreateWithFlags(&ev2, cudaEventDisableTiming);
    }
    const int smem = 3 * 32768;
    if (!attr_done) {
        cudaFuncSetAttribute(mma_kernel<0>, cudaFuncAttributeMaxDynamicSharedMemorySize, smem);
        cudaFuncSetAttribute(mma_kernel<1>, cudaFuncAttributeMaxDynamicSharedMemorySize, smem);
        cudaFuncSetAttribute(mma_kernel<2>, cudaFuncAttributeMaxDynamicSharedMemorySize, smem);
        cudaFuncSetAttribute(mma_kernel<3>, cudaFuncAttributeMaxDynamicSharedMemorySize, smem);
        attr_done = true;
    }

    // fork s1 (router path) off main
    cudaEventRecord(evF, 0);
    cudaStreamWaitEvent(s1, evF, 0);

    zero_cnt_kernel<<<1, 32, 0, s1>>>();                              // launch 0
    router_kernel<<<N_TOK / 4, 128, 0, s1>>>(x, wa);                  // launch 1
    cudaEventRecord(ev1, s1);

    // main: conversions for the up phase
    cvt_up_kernel<<<(8388608 + 2 * 33554432 + 2 * 4194304) / 1024, 256>>>(x, rg, rw1, sg, sw1); // launch 2
    cudaEventRecord(evCU, 0);

    // up-shared (no router dependency) — launch 3, ncu-profiled
    mma_kernel<0><<<dim3(N_TOK / 128, FF / 64, 2), 128, smem>>>(sgb, sb1, nullptr, nullptr);

    // up-routed needs router results
    cudaStreamWaitEvent(0, ev1, 0);
    mma_kernel<1><<<dim3(CAP / 128, FF / 64, NE), 128, smem>>>(rgb, rb1, nullptr, nullptr);     // launch 4

    // cvt_dn on s2 after cvt_up finished (avoid DRAM self-contention); overlaps mma0/mma1
    cudaStreamWaitEvent(s2, evCU, 0);
    cvt_dn_kernel<<<(33554432 + 4194304) / 1024, 256, 0, s2>>>(rw2, sw2);                       // launch 5
    cudaEventRecord(ev2, s2);

    // down phase
    cudaStreamWaitEvent(0, ev2, 0);
    mma_kernel<2><<<dim3(N_TOK / 128, DIM / 128, 1), 128, smem>>>(sb2, nullptr, x, out);        // launch 6
    mma_kernel<3><<<dim3(CAP / 128, DIM / 128, NE), 128, smem>>>(rb2, nullptr, nullptr, out);   // launch 7
}